// round 1
// baseline (speedup 1.0000x reference)
#include <cuda_runtime.h>
#include <cstdint>

#define GS 96
#define CC 64              // 8*8 elements per block
#define B_DIM 64
#define THREADS 256
#define WARPS (THREADS / 32)

// out[b][i][j][c][k]  (c = 0..63 flattened 8x8, k = 0..1)
// out[...][c][0] = x[b][i][c],  out[...][c][1] = x[b][j][c]
// -> per (b,i,j): 128 floats, pair-interleaved: (xi[0],xj[0],xi[1],xj[1],...)
__global__ void gcom_kernel(const float* __restrict__ x, float* __restrict__ out) {
    const int bi = blockIdx.x;           // 0 .. 64*96-1, encodes (b, i)
    const int b  = bi / GS;

    __shared__ float xi_s[CC];
    if (threadIdx.x < CC)
        xi_s[threadIdx.x] = __ldg(x + (size_t)bi * CC + threadIdx.x);
    __syncthreads();

    const int quad = threadIdx.x & 31;   // float4 index within a j-row (32 * 16B = 512B)
    const int wid  = threadIdx.x >> 5;   // warp id 0..7 -> j stride

    // xi pair for this lane (constant across j)
    const float2 xiv = reinterpret_cast<const float2*>(xi_s)[quad];

    const float2* __restrict__ xb =
        reinterpret_cast<const float2*>(x + (size_t)b * GS * CC);
    float4* __restrict__ op =
        reinterpret_cast<float4*>(out) + (size_t)bi * GS * 32;

    #pragma unroll
    for (int j = wid; j < GS; j += WARPS) {
        const float2 xjv = __ldg(xb + (size_t)j * 32 + quad);
        float4 v;
        v.x = xiv.x; v.y = xjv.x;        // (xi[2q],   xj[2q])
        v.z = xiv.y; v.w = xjv.y;        // (xi[2q+1], xj[2q+1])
        op[(size_t)j * 32 + quad] = v;
    }
}

extern "C" void kernel_launch(void* const* d_in, const int* in_sizes, int n_in,
                              void* d_out, int out_size) {
    const float* x = (const float*)d_in[0];
    float* out = (float*)d_out;
    gcom_kernel<<<B_DIM * GS, THREADS>>>(x, out);
}

// round 2
// speedup vs baseline: 1.0457x; 1.0457x over previous
#include <cuda_runtime.h>
#include <cstdint>

#define GS 96
#define CC 64              // 8*8 elements per block
#define B_DIM 64
#define THREADS 256
#define WARPS (THREADS / 32)

// out[b][i][j][c][k]  (c = 0..63 flattened 8x8, k = 0..1)
// out[...][c][0] = x[b][i][c],  out[...][c][1] = x[b][j][c]
// Per (b,i,j): 128 floats, pair-interleaved: (xi[0],xj[0],xi[1],xj[1],...)
__global__ void gcom_kernel(const float* __restrict__ x, float* __restrict__ out) {
    const int bi = blockIdx.x;           // encodes (b, i)
    const int b  = bi / GS;
    const int i  = bi - b * GS;

    // Stage all 96 blocks of this batch row in shared (96*64*4 = 24.5 KB)
    __shared__ float xs[GS * CC];
    {
        const float4* src = reinterpret_cast<const float4*>(x + (size_t)b * GS * CC);
        float4* dst = reinterpret_cast<float4*>(xs);
        #pragma unroll
        for (int t = threadIdx.x; t < GS * CC / 4; t += THREADS)
            dst[t] = __ldg(src + t);
    }
    __syncthreads();

    const int quad = threadIdx.x & 31;   // float4 index within a j-row (32*16B = 512B)
    const int wid  = threadIdx.x >> 5;   // warp id 0..7 -> j stride

    // xi pair for this lane (constant across j)
    const float2 xiv = reinterpret_cast<const float2*>(xs + i * CC)[quad];

    const float2* __restrict__ xs2 = reinterpret_cast<const float2*>(xs);
    float4* __restrict__ op =
        reinterpret_cast<float4*>(out) + (size_t)bi * GS * 32;

    #pragma unroll 4
    for (int j = wid; j < GS; j += WARPS) {
        const float2 xjv = xs2[j * 32 + quad];
        float4 v;
        v.x = xiv.x; v.y = xjv.x;        // (xi[2q],   xj[2q])
        v.z = xiv.y; v.w = xjv.y;        // (xi[2q+1], xj[2q+1])
        __stcs(op + (size_t)j * 32 + quad, v);   // streaming: evict-first
    }
}

extern "C" void kernel_launch(void* const* d_in, const int* in_sizes, int n_in,
                              void* d_out, int out_size) {
    const float* x = (const float*)d_in[0];
    float* out = (float*)d_out;
    gcom_kernel<<<B_DIM * GS, THREADS>>>(x, out);
}